// round 1
// baseline (speedup 1.0000x reference)
#include <cuda_runtime.h>
#include <cstdint>

#define Bx    2
#define Lx    2048
#define Dx    1024
#define Hx    16
#define DHx   64
#define CKx   64
#define NCH   32          // Lx / CKx
#define ROWSx 4096        // Bx * Lx
#define BHx   32          // Bx * Hx

// Scratch (device globals: no allocation allowed in kernel_launch)
__device__ float g_qkv[ROWSx * 3 * Dx];           // [4096, 3072]
__device__ float g_y[ROWSx * Dx];                 // [4096, 1024]
__device__ float g_M[BHx * NCH * DHx * DHx];      // per-chunk state contribs
__device__ float g_P[BHx * NCH * DHx * DHx];      // exclusive prefix states

// ---------------------------------------------------------------------------
// SGEMM (NT): C[M,N] = A[M,K] @ W[N,K]^T + bias[N]
// 128x128 block tile, BK=16, 256 threads, 8x8 per thread (2x2 of 4x4)
// ---------------------------------------------------------------------------
__global__ void __launch_bounds__(256) sgemm_nt_bias(
    const float* __restrict__ A, const float* __restrict__ W,
    const float* __restrict__ bias, float* __restrict__ C,
    int M, int N, int K)
{
    __shared__ float As[16][128];
    __shared__ float Bs[16][128];
    const int tid = threadIdx.x;
    const int tx = tid & 15, ty = tid >> 4;
    const int bm = blockIdx.y * 128, bn = blockIdx.x * 128;

    float acc[2][2][4][4];
    #pragma unroll
    for (int p = 0; p < 2; p++)
        #pragma unroll
        for (int q = 0; q < 2; q++)
            #pragma unroll
            for (int i = 0; i < 4; i++)
                #pragma unroll
                for (int j = 0; j < 4; j++)
                    acc[p][q][i][j] = 0.f;

    for (int k0 = 0; k0 < K; k0 += 16) {
        #pragma unroll
        for (int i = 0; i < 2; i++) {
            int e = tid + i * 256;            // 0..511
            int row = e >> 2, c4 = e & 3;     // row 0..127, c4 0..3
            float4 av = *(const float4*)(A + (size_t)(bm + row) * K + k0 + c4 * 4);
            As[c4 * 4 + 0][row] = av.x;
            As[c4 * 4 + 1][row] = av.y;
            As[c4 * 4 + 2][row] = av.z;
            As[c4 * 4 + 3][row] = av.w;
            float4 wv = *(const float4*)(W + (size_t)(bn + row) * K + k0 + c4 * 4);
            Bs[c4 * 4 + 0][row] = wv.x;
            Bs[c4 * 4 + 1][row] = wv.y;
            Bs[c4 * 4 + 2][row] = wv.z;
            Bs[c4 * 4 + 3][row] = wv.w;
        }
        __syncthreads();
        #pragma unroll
        for (int kk = 0; kk < 16; kk++) {
            float4 a0 = *(const float4*)&As[kk][ty * 4];
            float4 a1 = *(const float4*)&As[kk][64 + ty * 4];
            float4 b0 = *(const float4*)&Bs[kk][tx * 4];
            float4 b1 = *(const float4*)&Bs[kk][64 + tx * 4];
            float ar[2][4] = {{a0.x, a0.y, a0.z, a0.w}, {a1.x, a1.y, a1.z, a1.w}};
            float br[2][4] = {{b0.x, b0.y, b0.z, b0.w}, {b1.x, b1.y, b1.z, b1.w}};
            #pragma unroll
            for (int p = 0; p < 2; p++)
                #pragma unroll
                for (int q = 0; q < 2; q++)
                    #pragma unroll
                    for (int i = 0; i < 4; i++)
                        #pragma unroll
                        for (int j = 0; j < 4; j++)
                            acc[p][q][i][j] += ar[p][i] * br[q][j];
        }
        __syncthreads();
    }

    #pragma unroll
    for (int p = 0; p < 2; p++)
        #pragma unroll
        for (int i = 0; i < 4; i++) {
            int row = bm + p * 64 + ty * 4 + i;
            #pragma unroll
            for (int q = 0; q < 2; q++) {
                int col = bn + q * 64 + tx * 4;
                float4 bv = *(const float4*)(bias + col);
                float4 o;
                o.x = acc[p][q][i][0] + bv.x;
                o.y = acc[p][q][i][1] + bv.y;
                o.z = acc[p][q][i][2] + bv.z;
                o.w = acc[p][q][i][3] + bv.w;
                *(float4*)(C + (size_t)row * N + col) = o;
            }
        }
}

// ---------------------------------------------------------------------------
// Attention kernel A: per (bh, chunk) of 64 tokens:
//   y_intra = tril(Q K^T) V        -> g_y
//   M       = V^T K (64x64 state)  -> g_M
// 256 threads; 4x4 per-thread micro-tiles on 64x64 outputs.
// ---------------------------------------------------------------------------
__global__ void __launch_bounds__(256) attn_intra_kernel()
{
    __shared__ float sQt[64][64];   // q transposed [d][t]; later reused as V [t][c]
    __shared__ float sKt[64][64];   // k transposed [d][t] (pre-scaled)
    __shared__ float sS[64][64];    // scores [i][j]

    const int tid = threadIdx.x;
    const int tx = tid & 15, ty = tid >> 4;
    const int chunk = blockIdx.x, bh = blockIdx.y;
    const int b = bh >> 4, h = bh & 15;

    const float* qbase = g_qkv + ((size_t)(b * Lx + chunk * CKx)) * (3 * Dx) + h * DHx;
    const float* kbase = qbase + Dx;
    const float* vbase = qbase + 2 * Dx;
    const float sc = 0.125f;   // 1/sqrt(64)

    #pragma unroll
    for (int i = 0; i < 4; i++) {
        int e = tid + i * 256;        // 0..1023
        int row = e >> 4, c4 = e & 15;
        float4 qv = *(const float4*)(qbase + (size_t)row * (3 * Dx) + c4 * 4);
        sQt[c4 * 4 + 0][row] = qv.x;
        sQt[c4 * 4 + 1][row] = qv.y;
        sQt[c4 * 4 + 2][row] = qv.z;
        sQt[c4 * 4 + 3][row] = qv.w;
        float4 kv = *(const float4*)(kbase + (size_t)row * (3 * Dx) + c4 * 4);
        sKt[c4 * 4 + 0][row] = kv.x * sc;
        sKt[c4 * 4 + 1][row] = kv.y * sc;
        sKt[c4 * 4 + 2][row] = kv.z * sc;
        sKt[c4 * 4 + 3][row] = kv.w * sc;
    }
    __syncthreads();

    // Scores S[i][j] = sum_d q[i][d] k[j][d], i = ty*4.., j = tx*4..
    float accS[4][4] = {};
    #pragma unroll 8
    for (int d = 0; d < 64; d++) {
        float4 a = *(const float4*)&sQt[d][ty * 4];
        float4 k4 = *(const float4*)&sKt[d][tx * 4];
        float ar[4] = {a.x, a.y, a.z, a.w};
        float kr[4] = {k4.x, k4.y, k4.z, k4.w};
        #pragma unroll
        for (int i = 0; i < 4; i++)
            #pragma unroll
            for (int j = 0; j < 4; j++)
                accS[i][j] += ar[i] * kr[j];
    }
    #pragma unroll
    for (int ii = 0; ii < 4; ii++) {
        int i = ty * 4 + ii;
        int j0 = tx * 4;
        float4 o;
        o.x = (i >= j0 + 0) ? accS[ii][0] : 0.f;
        o.y = (i >= j0 + 1) ? accS[ii][1] : 0.f;
        o.z = (i >= j0 + 2) ? accS[ii][2] : 0.f;
        o.w = (i >= j0 + 3) ? accS[ii][3] : 0.f;
        *(float4*)&sS[i][j0] = o;
    }
    __syncthreads();   // all sQt reads done; safe to reuse as V

    float (*sV)[64] = sQt;
    #pragma unroll
    for (int i = 0; i < 4; i++) {
        int e = tid + i * 256;
        int row = e >> 4, c4 = e & 15;
        *(float4*)&sV[row][c4 * 4] = *(const float4*)(vbase + (size_t)row * (3 * Dx) + c4 * 4);
    }
    __syncthreads();

    // y_intra[i][c] = sum_j S[i][j] V[j][c];  i = ty*4.., c = tx*4..
    float accY[4][4] = {};
    #pragma unroll 8
    for (int j = 0; j < 64; j++) {
        float sa[4];
        #pragma unroll
        for (int ii = 0; ii < 4; ii++) sa[ii] = sS[ty * 4 + ii][j];
        float4 v4 = *(const float4*)&sV[j][tx * 4];
        float vr[4] = {v4.x, v4.y, v4.z, v4.w};
        #pragma unroll
        for (int ii = 0; ii < 4; ii++)
            #pragma unroll
            for (int cc = 0; cc < 4; cc++)
                accY[ii][cc] += sa[ii] * vr[cc];
    }

    // M[a][b] = sum_t V[t][a] K[t][b];  a = tx*4.., b = ty*4..
    float accM[4][4] = {};
    #pragma unroll 8
    for (int t = 0; t < 64; t++) {
        float4 v4 = *(const float4*)&sV[t][tx * 4];
        float va[4] = {v4.x, v4.y, v4.z, v4.w};
        float kb[4];
        #pragma unroll
        for (int jj = 0; jj < 4; jj++) kb[jj] = sKt[ty * 4 + jj][t];
        #pragma unroll
        for (int ii = 0; ii < 4; ii++)
            #pragma unroll
            for (int jj = 0; jj < 4; jj++)
                accM[ii][jj] += va[ii] * kb[jj];
    }

    // write y_intra
    float* ybase = g_y + ((size_t)(b * Lx + chunk * CKx)) * Dx + h * DHx;
    #pragma unroll
    for (int ii = 0; ii < 4; ii++) {
        int row = ty * 4 + ii;
        float4 o = {accY[ii][0], accY[ii][1], accY[ii][2], accY[ii][3]};
        *(float4*)(ybase + (size_t)row * Dx + tx * 4) = o;
    }

    __syncthreads();   // sS reads done; reuse for coalesced M staging
    #pragma unroll
    for (int ii = 0; ii < 4; ii++)
        #pragma unroll
        for (int jj = 0; jj < 4; jj++)
            sS[tx * 4 + ii][ty * 4 + jj] = accM[ii][jj];
    __syncthreads();

    float* Mbase = g_M + ((size_t)(bh * NCH + chunk)) * (DHx * DHx);
    #pragma unroll
    for (int i = 0; i < 4; i++) {
        int e = tid + i * 256;
        int row = e >> 4, c4 = e & 15;
        *(float4*)(Mbase + row * 64 + c4 * 4) = *(const float4*)&sS[row][c4 * 4];
    }
}

// ---------------------------------------------------------------------------
// Exclusive prefix over chunks: P[c] = sum_{j<c} M[j], per (bh, element)
// ---------------------------------------------------------------------------
__global__ void __launch_bounds__(256) prefix_kernel()
{
    const int bh = blockIdx.y;
    const int e = blockIdx.x * 256 + threadIdx.x;   // 0..4095
    size_t base = (size_t)bh * NCH * (DHx * DHx) + e;
    float acc = 0.f;
    #pragma unroll 8
    for (int c = 0; c < NCH; c++) {
        g_P[base + (size_t)c * (DHx * DHx)] = acc;
        acc += g_M[base + (size_t)c * (DHx * DHx)];
    }
}

// ---------------------------------------------------------------------------
// Attention kernel C: y[t][c] += sum_b q[t][b] * P[c][b]
// ---------------------------------------------------------------------------
__global__ void __launch_bounds__(256) attn_inter_kernel()
{
    __shared__ float sQt[64][64];   // [b][t]
    __shared__ float sPt[64][64];   // [b][c]

    const int tid = threadIdx.x;
    const int tx = tid & 15, ty = tid >> 4;
    const int chunk = blockIdx.x, bh = blockIdx.y;
    const int b = bh >> 4, h = bh & 15;

    const float* qbase = g_qkv + ((size_t)(b * Lx + chunk * CKx)) * (3 * Dx) + h * DHx;
    const float* Pbase = g_P + ((size_t)(bh * NCH + chunk)) * (DHx * DHx);

    #pragma unroll
    for (int i = 0; i < 4; i++) {
        int e = tid + i * 256;
        int row = e >> 4, c4 = e & 15;
        float4 qv = *(const float4*)(qbase + (size_t)row * (3 * Dx) + c4 * 4);
        sQt[c4 * 4 + 0][row] = qv.x;
        sQt[c4 * 4 + 1][row] = qv.y;
        sQt[c4 * 4 + 2][row] = qv.z;
        sQt[c4 * 4 + 3][row] = qv.w;
        float4 pv = *(const float4*)(Pbase + (size_t)row * 64 + c4 * 4);
        sPt[c4 * 4 + 0][row] = pv.x;
        sPt[c4 * 4 + 1][row] = pv.y;
        sPt[c4 * 4 + 2][row] = pv.z;
        sPt[c4 * 4 + 3][row] = pv.w;
    }
    __syncthreads();

    float acc[4][4] = {};   // [t][c]; t = ty*4.., c = tx*4..
    #pragma unroll 8
    for (int bb = 0; bb < 64; bb++) {
        float4 a = *(const float4*)&sQt[bb][ty * 4];
        float4 p = *(const float4*)&sPt[bb][tx * 4];
        float ar[4] = {a.x, a.y, a.z, a.w};
        float pr[4] = {p.x, p.y, p.z, p.w};
        #pragma unroll
        for (int i = 0; i < 4; i++)
            #pragma unroll
            for (int j = 0; j < 4; j++)
                acc[i][j] += ar[i] * pr[j];
    }

    float* ybase = g_y + ((size_t)(b * Lx + chunk * CKx)) * Dx + h * DHx;
    #pragma unroll
    for (int ii = 0; ii < 4; ii++) {
        float4 old = *(const float4*)(ybase + (size_t)(ty * 4 + ii) * Dx + tx * 4);
        old.x += acc[ii][0];
        old.y += acc[ii][1];
        old.z += acc[ii][2];
        old.w += acc[ii][3];
        *(float4*)(ybase + (size_t)(ty * 4 + ii) * Dx + tx * 4) = old;
    }
}

// ---------------------------------------------------------------------------
extern "C" void kernel_launch(void* const* d_in, const int* in_sizes, int n_in,
                              void* d_out, int out_size)
{
    const float* x      = (const float*)d_in[0];   // [2,2048,1024]
    const float* Wqkv_w = (const float*)d_in[1];   // [3072,1024]
    const float* Wqkv_b = (const float*)d_in[2];   // [3072]
    const float* out_w  = (const float*)d_in[3];   // [1024,1024]
    const float* out_b  = (const float*)d_in[4];   // [1024]
    float* out = (float*)d_out;                    // [2,2048,1024]

    float* qkv_ptr = nullptr;
    float* y_ptr = nullptr;
    cudaGetSymbolAddress((void**)&qkv_ptr, g_qkv);
    cudaGetSymbolAddress((void**)&y_ptr, g_y);

    // 1. QKV projection: [4096,1024] @ [3072,1024]^T + b -> [4096,3072]
    sgemm_nt_bias<<<dim3(3072 / 128, ROWSx / 128), 256>>>(
        x, Wqkv_w, Wqkv_b, qkv_ptr, ROWSx, 3 * Dx, Dx);

    // 2a. Intra-chunk attention + per-chunk states
    attn_intra_kernel<<<dim3(NCH, BHx), 256>>>();

    // 2b. Exclusive prefix of states
    prefix_kernel<<<dim3(16, BHx), 256>>>();

    // 2c. Inter-chunk contribution
    attn_inter_kernel<<<dim3(NCH, BHx), 256>>>();

    // 3. Output projection: [4096,1024] @ [1024,1024]^T + b -> d_out
    sgemm_nt_bias<<<dim3(Dx / 128, ROWSx / 128), 256>>>(
        y_ptr, out_w, out_b, out, ROWSx, Dx, Dx);
}

// round 3
// speedup vs baseline: 2.5724x; 2.5724x over previous
#include <cuda_runtime.h>
#include <cstdint>

#define Bx    2
#define Lx    2048
#define Dx    1024
#define Hx    16
#define DHx   64
#define CKx   64
#define NCH   32          // Lx / CKx
#define ROWSx 4096        // Bx * Lx
#define BHx   32          // Bx * Hx

// Scratch (device globals: no allocation allowed in kernel_launch)
__device__ float g_qkv[ROWSx * 3 * Dx];           // [4096, 3072]
__device__ float g_y[ROWSx * Dx];                 // [4096, 1024]
__device__ float g_M[BHx * NCH * DHx * DHx];      // per-chunk state contribs
__device__ float g_P[BHx * NCH * DHx * DHx];      // exclusive prefix states

// ============================================================================
// helpers (all non-"a" instructions: sm_80/sm_75 era, safe on plain sm_103)
// ============================================================================
__device__ __forceinline__ uint32_t smem_u32(const void* p) {
    uint32_t a;
    asm("{ .reg .u64 t; cvta.to.shared.u64 t, %1; cvt.u32.u64 %0, t; }"
        : "=r"(a) : "l"(p));
    return a;
}

#define CP16(dst, src) \
    asm volatile("cp.async.cg.shared.global [%0], [%1], 16;" :: "r"(dst), "l"(src) : "memory")
#define CP_COMMIT() asm volatile("cp.async.commit_group;" ::: "memory")
#define CP_WAIT1()  asm volatile("cp.async.wait_group 1;" ::: "memory")

#define LDSM4(r0, r1, r2, r3, addr) \
    asm volatile("ldmatrix.sync.aligned.m8n8.x4.shared.b16 {%0,%1,%2,%3}, [%4];" \
                 : "=r"(r0), "=r"(r1), "=r"(r2), "=r"(r3) : "r"(addr))

#define CVT_TF32(x) asm volatile("cvt.rna.tf32.f32 %0, %0;" : "+r"(x))

#define MMA_TF32(d, a, b) \
    asm volatile("mma.sync.aligned.m16n8k8.row.col.f32.tf32.tf32.f32 " \
                 "{%0,%1,%2,%3}, {%4,%5,%6,%7}, {%8,%9}, {%0,%1,%2,%3};" \
                 : "+f"((d)[0]), "+f"((d)[1]), "+f"((d)[2]), "+f"((d)[3]) \
                 : "r"((a)[0]), "r"((a)[1]), "r"((a)[2]), "r"((a)[3]), \
                   "r"((b)[0]), "r"((b)[1]))

// ============================================================================
// tf32 tensor-core GEMM (NT): C[M,N] = A[M,K] @ W[N,K]^T + bias[N]
// CTA 128x128, BK=32, 256 thr (8 warps as 4x2, warp tile 32x64), 3-stage cp.async
// smem per stage: A 128x32 f32 (16KB) + B 128x32 f32 (16KB), XOR-swizzled 16B chunks
// ============================================================================
#define TBM 128
#define TBN 128
#define TBK 32
#define TSTG_BYTES (TBM * TBK * 4 + TBN * TBK * 4)   // 32768
#define TSMEM_TOTAL (3 * TSTG_BYTES)                 // 98304

__device__ __forceinline__ void tload(uint32_t stg, const float* __restrict__ A,
                                      const float* __restrict__ W, int K,
                                      int bm, int bn, int k0, int tid)
{
    #pragma unroll
    for (int j = 0; j < 4; j++) {
        int e = tid + j * 256;
        int r = e >> 3, c16 = e & 7;
        uint32_t dst = stg + (uint32_t)(r * 128 + ((c16 ^ (r & 7)) << 4));
        CP16(dst, A + (size_t)(bm + r) * K + k0 + c16 * 4);
    }
    #pragma unroll
    for (int j = 0; j < 4; j++) {
        int e = tid + j * 256;
        int r = e >> 3, c16 = e & 7;
        uint32_t dst = stg + 16384u + (uint32_t)(r * 128 + ((c16 ^ (r & 7)) << 4));
        CP16(dst, W + (size_t)(bn + r) * K + k0 + c16 * 4);
    }
}

__global__ void __launch_bounds__(256) gemm_tc_bias(
    const float* __restrict__ A, const float* __restrict__ W,
    const float* __restrict__ bias, float* __restrict__ C,
    int M, int N, int K)
{
    extern __shared__ char smem[];
    const uint32_t sb = smem_u32(smem);
    const int tid = threadIdx.x;
    const int lane = tid & 31, wid = tid >> 5;
    const int wm = wid & 3, wn = wid >> 2;
    const int bm = blockIdx.y * TBM;
    const int bn = blockIdx.x * TBN;
    const int NK = K / TBK;

    // ldmatrix lane geometry (same pattern for A and B):
    // x4 covers 16 rows x 8 k-cols; lane row = lane&15, k-chunk add = lane>>4
    const int lrow = lane & 15;
    const int lkc  = lane >> 4;
    const int l7   = lrow & 7;

    uint32_t aRow[2], bRow[4];
    #pragma unroll
    for (int mt = 0; mt < 2; mt++) aRow[mt] = (uint32_t)((wm * 32 + mt * 16 + lrow) * 128);
    #pragma unroll
    for (int p = 0; p < 4; p++)    bRow[p] = (uint32_t)((wn * 64 + p * 16 + lrow) * 128);

    float d[2][8][4];
    #pragma unroll
    for (int mt = 0; mt < 2; mt++)
        #pragma unroll
        for (int nt = 0; nt < 8; nt++)
            #pragma unroll
            for (int i = 0; i < 4; i++) d[mt][nt][i] = 0.f;

    // Prologue: chunks 0,1 into stages 0,1
    tload(sb, A, W, K, bm, bn, 0, tid);
    CP_COMMIT();
    tload(sb + TSTG_BYTES, A, W, K, bm, bn, TBK, tid);
    CP_COMMIT();

    int stage = 0;
    for (int i = 0; i < NK; i++) {
        CP_WAIT1();
        __syncthreads();
        // prefetch chunk i+2 into the stage freed at iter i-1
        if (i + 2 < NK) {
            int s2 = (stage + 2 == 3) ? 2 : (stage + 2) - ((stage + 2 >= 3) ? 3 : 0);
            tload(sb + (uint32_t)(((stage + 2) % 3) * TSTG_BYTES), A, W, K, bm, bn,
                  (i + 2) * TBK, tid);
            (void)s2;
        }
        CP_COMMIT();   // uniform group count (empty group near the tail)

        const uint32_t sA = sb + (uint32_t)(stage * TSTG_BYTES);
        const uint32_t sB = sA + 16384u;

        #pragma unroll
        for (int ks = 0; ks < 4; ks++) {
            const int kc = ks * 2;                 // 16B-chunk base of this k8
            const uint32_t swzA = (uint32_t)(((kc + lkc) ^ l7) << 4);

            uint32_t a[2][4];
            #pragma unroll
            for (int mt = 0; mt < 2; mt++)
                LDSM4(a[mt][0], a[mt][1], a[mt][2], a[mt][3], sA + aRow[mt] + swzA);

            uint32_t b[8][2];
            #pragma unroll
            for (int p = 0; p < 4; p++) {
                uint32_t r0, r1, r2, r3;
                LDSM4(r0, r1, r2, r3, sB + bRow[p] + swzA);
                b[2 * p][0] = r0; b[2 * p + 1][0] = r1;
                b[2 * p][1] = r2; b[2 * p + 1][1] = r3;
            }

            #pragma unroll
            for (int mt = 0; mt < 2; mt++)
                #pragma unroll
                for (int q = 0; q < 4; q++) CVT_TF32(a[mt][q]);
            #pragma unroll
            for (int nt = 0; nt < 8; nt++) {
                CVT_TF32(b[nt][0]);
                CVT_TF32(b[nt][1]);
            }

            #pragma unroll
            for (int mt = 0; mt < 2; mt++)
                #pragma unroll
                for (int nt = 0; nt < 8; nt++)
                    MMA_TF32(d[mt][nt], a[mt], b[nt]);
        }
        stage = (stage + 1 == 3) ? 0 : stage + 1;
    }

    // Epilogue: fragment c mapping: c0,c1 -> (row=lane>>2, col=(lane&3)*2 .. +1),
    // c2,c3 -> row+8
    const int erow = lane >> 2;
    const int ecol = (lane & 3) * 2;
    #pragma unroll
    for (int mt = 0; mt < 2; mt++) {
        const int r0 = bm + wm * 32 + mt * 16 + erow;
        #pragma unroll
        for (int nt = 0; nt < 8; nt++) {
            const int c = bn + wn * 64 + nt * 8 + ecol;
            float2 bv = *(const float2*)(bias + c);
            float2 o0 = {d[mt][nt][0] + bv.x, d[mt][nt][1] + bv.y};
            float2 o1 = {d[mt][nt][2] + bv.x, d[mt][nt][3] + bv.y};
            *(float2*)(C + (size_t)r0 * N + c) = o0;
            *(float2*)(C + (size_t)(r0 + 8) * N + c) = o1;
        }
    }
}

// ---------------------------------------------------------------------------
// Attention kernel A: per (bh, chunk) of 64 tokens:
//   y_intra = tril(Q K^T) V        -> g_y
//   M       = V^T K (64x64 state)  -> g_M
// ---------------------------------------------------------------------------
__global__ void __launch_bounds__(256) attn_intra_kernel()
{
    __shared__ float sQt[64][64];
    __shared__ float sKt[64][64];
    __shared__ float sS[64][64];

    const int tid = threadIdx.x;
    const int tx = tid & 15, ty = tid >> 4;
    const int chunk = blockIdx.x, bh = blockIdx.y;
    const int b = bh >> 4, h = bh & 15;

    const float* qbase = g_qkv + ((size_t)(b * Lx + chunk * CKx)) * (3 * Dx) + h * DHx;
    const float* kbase = qbase + Dx;
    const float* vbase = qbase + 2 * Dx;
    const float sc = 0.125f;

    #pragma unroll
    for (int i = 0; i < 4; i++) {
        int e = tid + i * 256;
        int row = e >> 4, c4 = e & 15;
        float4 qv = *(const float4*)(qbase + (size_t)row * (3 * Dx) + c4 * 4);
        sQt[c4 * 4 + 0][row] = qv.x;
        sQt[c4 * 4 + 1][row] = qv.y;
        sQt[c4 * 4 + 2][row] = qv.z;
        sQt[c4 * 4 + 3][row] = qv.w;
        float4 kv = *(const float4*)(kbase + (size_t)row * (3 * Dx) + c4 * 4);
        sKt[c4 * 4 + 0][row] = kv.x * sc;
        sKt[c4 * 4 + 1][row] = kv.y * sc;
        sKt[c4 * 4 + 2][row] = kv.z * sc;
        sKt[c4 * 4 + 3][row] = kv.w * sc;
    }
    __syncthreads();

    float accS[4][4] = {};
    #pragma unroll 8
    for (int d = 0; d < 64; d++) {
        float4 a = *(const float4*)&sQt[d][ty * 4];
        float4 k4 = *(const float4*)&sKt[d][tx * 4];
        float ar[4] = {a.x, a.y, a.z, a.w};
        float kr[4] = {k4.x, k4.y, k4.z, k4.w};
        #pragma unroll
        for (int i = 0; i < 4; i++)
            #pragma unroll
            for (int j = 0; j < 4; j++)
                accS[i][j] += ar[i] * kr[j];
    }
    #pragma unroll
    for (int ii = 0; ii < 4; ii++) {
        int i = ty * 4 + ii;
        int j0 = tx * 4;
        float4 o;
        o.x = (i >= j0 + 0) ? accS[ii][0] : 0.f;
        o.y = (i >= j0 + 1) ? accS[ii][1] : 0.f;
        o.z = (i >= j0 + 2) ? accS[ii][2] : 0.f;
        o.w = (i >= j0 + 3) ? accS[ii][3] : 0.f;
        *(float4*)&sS[i][j0] = o;
    }
    __syncthreads();

    float (*sV)[64] = sQt;
    #pragma unroll
    for (int i = 0; i < 4; i++) {
        int e = tid + i * 256;
        int row = e >> 4, c4 = e & 15;
        *(float4*)&sV[row][c4 * 4] = *(const float4*)(vbase + (size_t)row * (3 * Dx) + c4 * 4);
    }
    __syncthreads();

    float accY[4][4] = {};
    #pragma unroll 8
    for (int j = 0; j < 64; j++) {
        float sa[4];
        #pragma unroll
        for (int ii = 0; ii < 4; ii++) sa[ii] = sS[ty * 4 + ii][j];
        float4 v4 = *(const float4*)&sV[j][tx * 4];
        float vr[4] = {v4.x, v4.y, v4.z, v4.w};
        #pragma unroll
        for (int ii = 0; ii < 4; ii++)
            #pragma unroll
            for (int cc = 0; cc < 4; cc++)
                accY[ii][cc] += sa[ii] * vr[cc];
    }

    float accM[4][4] = {};
    #pragma unroll 8
    for (int t = 0; t < 64; t++) {
        float4 v4 = *(const float4*)&sV[t][tx * 4];
        float va[4] = {v4.x, v4.y, v4.z, v4.w};
        float kb[4];
        #pragma unroll
        for (int jj = 0; jj < 4; jj++) kb[jj] = sKt[ty * 4 + jj][t];
        #pragma unroll
        for (int ii = 0; ii < 4; ii++)
            #pragma unroll
            for (int jj = 0; jj < 4; jj++)
                accM[ii][jj] += va[ii] * kb[jj];
    }

    float* ybase = g_y + ((size_t)(b * Lx + chunk * CKx)) * Dx + h * DHx;
    #pragma unroll
    for (int ii = 0; ii < 4; ii++) {
        int row = ty * 4 + ii;
        float4 o = {accY[ii][0], accY[ii][1], accY[ii][2], accY[ii][3]};
        *(float4*)(ybase + (size_t)row * Dx + tx * 4) = o;
    }

    __syncthreads();
    #pragma unroll
    for (int ii = 0; ii < 4; ii++)
        #pragma unroll
        for (int jj = 0; jj < 4; jj++)
            sS[tx * 4 + ii][ty * 4 + jj] = accM[ii][jj];
    __syncthreads();

    float* Mbase = g_M + ((size_t)(bh * NCH + chunk)) * (DHx * DHx);
    #pragma unroll
    for (int i = 0; i < 4; i++) {
        int e = tid + i * 256;
        int row = e >> 4, c4 = e & 15;
        *(float4*)(Mbase + row * 64 + c4 * 4) = *(const float4*)&sS[row][c4 * 4];
    }
}

// ---------------------------------------------------------------------------
// Exclusive prefix over chunks: P[c] = sum_{j<c} M[j]
// ---------------------------------------------------------------------------
__global__ void __launch_bounds__(256) prefix_kernel()
{
    const int bh = blockIdx.y;
    const int e = blockIdx.x * 256 + threadIdx.x;
    size_t base = (size_t)bh * NCH * (DHx * DHx) + e;
    float acc = 0.f;
    #pragma unroll 8
    for (int c = 0; c < NCH; c++) {
        g_P[base + (size_t)c * (DHx * DHx)] = acc;
        acc += g_M[base + (size_t)c * (DHx * DHx)];
    }
}

// ---------------------------------------------------------------------------
// Attention kernel C: y[t][c] += sum_b q[t][b] * P[c][b]
// ---------------------------------------------------------------------------
__global__ void __launch_bounds__(256) attn_inter_kernel()
{
    __shared__ float sQt[64][64];
    __shared__ float sPt[64][64];

    const int tid = threadIdx.x;
    const int tx = tid & 15, ty = tid >> 4;
    const int chunk = blockIdx.x, bh = blockIdx.y;
    const int b = bh >> 4, h = bh & 15;

    const float* qbase = g_qkv + ((size_t)(b * Lx + chunk * CKx)) * (3 * Dx) + h * DHx;
    const float* Pbase = g_P + ((size_t)(bh * NCH + chunk)) * (DHx * DHx);

    #pragma unroll
    for (int i = 0; i < 4; i++) {
        int e = tid + i * 256;
        int row = e >> 4, c4 = e & 15;
        float4 qv = *(const float4*)(qbase + (size_t)row * (3 * Dx) + c4 * 4);
        sQt[c4 * 4 + 0][row] = qv.x;
        sQt[c4 * 4 + 1][row] = qv.y;
        sQt[c4 * 4 + 2][row] = qv.z;
        sQt[c4 * 4 + 3][row] = qv.w;
        float4 pv = *(const float4*)(Pbase + (size_t)row * 64 + c4 * 4);
        sPt[c4 * 4 + 0][row] = pv.x;
        sPt[c4 * 4 + 1][row] = pv.y;
        sPt[c4 * 4 + 2][row] = pv.z;
        sPt[c4 * 4 + 3][row] = pv.w;
    }
    __syncthreads();

    float acc[4][4] = {};
    #pragma unroll 8
    for (int bb = 0; bb < 64; bb++) {
        float4 a = *(const float4*)&sQt[bb][ty * 4];
        float4 p = *(const float4*)&sPt[bb][tx * 4];
        float ar[4] = {a.x, a.y, a.z, a.w};
        float pr[4] = {p.x, p.y, p.z, p.w};
        #pragma unroll
        for (int i = 0; i < 4; i++)
            #pragma unroll
            for (int j = 0; j < 4; j++)
                acc[i][j] += ar[i] * pr[j];
    }

    float* ybase = g_y + ((size_t)(b * Lx + chunk * CKx)) * Dx + h * DHx;
    #pragma unroll
    for (int ii = 0; ii < 4; ii++) {
        float4 old = *(const float4*)(ybase + (size_t)(ty * 4 + ii) * Dx + tx * 4);
        old.x += acc[ii][0];
        old.y += acc[ii][1];
        old.z += acc[ii][2];
        old.w += acc[ii][3];
        *(float4*)(ybase + (size_t)(ty * 4 + ii) * Dx + tx * 4) = old;
    }
}

// ---------------------------------------------------------------------------
extern "C" void kernel_launch(void* const* d_in, const int* in_sizes, int n_in,
                              void* d_out, int out_size)
{
    const float* x      = (const float*)d_in[0];   // [2,2048,1024]
    const float* Wqkv_w = (const float*)d_in[1];   // [3072,1024]
    const float* Wqkv_b = (const float*)d_in[2];   // [3072]
    const float* out_w  = (const float*)d_in[3];   // [1024,1024]
    const float* out_b  = (const float*)d_in[4];   // [1024]
    float* out = (float*)d_out;                    // [2,2048,1024]

    float* qkv_ptr = nullptr;
    float* y_ptr = nullptr;
    cudaGetSymbolAddress((void**)&qkv_ptr, g_qkv);
    cudaGetSymbolAddress((void**)&y_ptr, g_y);

    cudaFuncSetAttribute(gemm_tc_bias,
                         cudaFuncAttributeMaxDynamicSharedMemorySize, TSMEM_TOTAL);

    // 1. QKV projection: [4096,1024] @ [3072,1024]^T + b -> [4096,3072]
    gemm_tc_bias<<<dim3(3072 / TBN, ROWSx / TBM), 256, TSMEM_TOTAL>>>(
        x, Wqkv_w, Wqkv_b, qkv_ptr, ROWSx, 3 * Dx, Dx);

    // 2a. Intra-chunk attention + per-chunk states
    attn_intra_kernel<<<dim3(NCH, BHx), 256>>>();

    // 2b. Exclusive prefix of states
    prefix_kernel<<<dim3(16, BHx), 256>>>();

    // 2c. Inter-chunk contribution
    attn_inter_kernel<<<dim3(NCH, BHx), 256>>>();

    // 3. Output projection: [4096,1024] @ [1024,1024]^T + b -> d_out
    gemm_tc_bias<<<dim3(Dx / TBN, ROWSx / TBM), 256, TSMEM_TOTAL>>>(
        y_ptr, out_w, out_b, out, ROWSx, Dx, Dx);
}